// round 5
// baseline (speedup 1.0000x reference)
#include <cuda_runtime.h>

// Problem constants (fixed by the dataset)
#define E_N 100000
#define R_N 64
#define I_N 256
#define O_N 256

#define TILE_E 64   // entities per block in the main kernel

// Scratch for W_sum[r][o] = sum_i W[r][i][o]  (static device global: no allocation)
__device__ float g_wsum[R_N * O_N];

// ---------------------------------------------------------------------------
// Kernel 1: W reduction over i.  grid=(R_N), block=1024.
// thread (c,o): c = i-chunk (4 chunks of 64), o = output column.
// Coalesced: consecutive tid -> consecutive o.
// ---------------------------------------------------------------------------
__global__ void __launch_bounds__(1024) wsum_kernel(const float* __restrict__ W) {
    __shared__ float red[4][256];
    const int r = blockIdx.x;
    const int o = threadIdx.x & 255;
    const int c = threadIdx.x >> 8;   // 0..3

    const float* p = W + (size_t)r * (I_N * O_N) + (size_t)c * 64 * O_N + o;
    float acc = 0.0f;
#pragma unroll 16
    for (int i = 0; i < 64; ++i) acc += p[i * O_N];

    red[c][o] = acc;
    __syncthreads();
    if (c == 0) {
        g_wsum[r * O_N + o] = (red[0][o] + red[1][o]) + (red[2][o] + red[3][o]);
    }
}

// ---------------------------------------------------------------------------
// Kernel 2: per-entity  out[e, :] = x_sum[e] * (1/cs[e, :]) @ W_sum
// block = 256 threads, TILE_E = 64 entities.
// Micro-tile per thread: 8 entities x 8 output columns, packed f32x2 FMA.
// Shared: W_sum (64KB) + recip-cs tile (16KB) + x_sum (256B) = 82176 B dynamic.
// ---------------------------------------------------------------------------
__global__ void __launch_bounds__(256, 2) rgcn_kernel(
    const float* __restrict__ x, const float* __restrict__ cs,
    float* __restrict__ out) {
    extern __shared__ float sm[];
    float* ws    = sm;                      // [64][256]
    float* a_sh  = ws + R_N * O_N;          // [TILE_E][64]  (1/cs)
    float* xs_sh = a_sh + TILE_E * R_N;     // [TILE_E]

    const int tid  = threadIdx.x;
    const int lane = tid & 31;
    const int wid  = tid >> 5;              // 8 warps
    const int e0   = blockIdx.x * TILE_E;

    // ---- stage W_sum into shared (conflict-free float4 copy, L2-hot) ----
    {
        const float4* src = (const float4*)g_wsum;
        float4* dst = (float4*)ws;
#pragma unroll
        for (int k = 0; k < 16; ++k) dst[tid + k * 256] = src[tid + k * 256];
    }

    // ---- stage 1/cs tile: a_sh[e][r], coalesced float4 load + cf store ----
    {
        const float4* csrc = (const float4*)cs;
        float4* adst = (float4*)a_sh;
#pragma unroll
        for (int k = 0; k < 4; ++k) {
            int l = tid + k * 256;          // float4 index in tile: 0..1023
            int e = l >> 4;                 // 16 float4 per entity row
            float4 v;
            if (e0 + e < E_N) v = csrc[(size_t)(e0 + e) * 16 + (l & 15)];
            else              v = make_float4(1.f, 1.f, 1.f, 1.f);
            adst[l] = make_float4(1.f / v.x, 1.f / v.y, 1.f / v.z, 1.f / v.w);
        }
    }

    // ---- x_sum: warp `wid` handles entities wid*8 .. wid*8+7 ----
#pragma unroll
    for (int q = 0; q < 8; ++q) {
        const int el = wid * 8 + q;
        const int e  = e0 + el;
        float s = 0.0f;
        if (e < E_N) {
            const float4* xr = (const float4*)(x + (size_t)e * I_N);
            float4 v1 = xr[lane];
            float4 v2 = xr[lane + 32];
            s = ((v1.x + v1.y) + (v1.z + v1.w)) + ((v2.x + v2.y) + (v2.z + v2.w));
        }
#pragma unroll
        for (int off = 16; off > 0; off >>= 1)
            s += __shfl_xor_sync(0xffffffffu, s, off);
        if (lane == 0) xs_sh[el] = s;
    }
    __syncthreads();

    // ---- main GEMM: thread = 8 entities (warp's group) x 8 columns ----
    const int eb = wid * 8;                 // entity base for this warp
    const int tx = lane;                    // column fragment index

    unsigned long long acc[8][4];
#pragma unroll
    for (int j = 0; j < 8; ++j)
#pragma unroll
        for (int p = 0; p < 4; ++p) acc[j][p] = 0ull;

    // ws viewed as pairs: row = 256 floats = 64 ulonglong2.
    // b fragment: floats [tx*4 .. tx*4+3] and [128+tx*4 .. 128+tx*4+3]
    const ulonglong2* wsv = (const ulonglong2*)ws;

#pragma unroll 4
    for (int r = 0; r < R_N; ++r) {
        const ulonglong2 b0 = wsv[r * 64 + tx];
        const ulonglong2 b1 = wsv[r * 64 + tx + 32];
#pragma unroll
        for (int j = 0; j < 8; ++j) {
            const float a = a_sh[(eb + j) * R_N + r];   // uniform broadcast
            unsigned long long ap;
            asm("mov.b64 %0, {%1, %1};" : "=l"(ap) : "f"(a));
            asm("fma.rn.f32x2 %0, %1, %2, %0;" : "+l"(acc[j][0]) : "l"(ap), "l"(b0.x));
            asm("fma.rn.f32x2 %0, %1, %2, %0;" : "+l"(acc[j][1]) : "l"(ap), "l"(b0.y));
            asm("fma.rn.f32x2 %0, %1, %2, %0;" : "+l"(acc[j][2]) : "l"(ap), "l"(b1.x));
            asm("fma.rn.f32x2 %0, %1, %2, %0;" : "+l"(acc[j][3]) : "l"(ap), "l"(b1.y));
        }
    }

    // ---- epilogue: scale by x_sum and store (coalesced float4) ----
#pragma unroll
    for (int j = 0; j < 8; ++j) {
        const int e = e0 + eb + j;
        if (e < E_N) {
            const float s = xs_sh[eb + j];
            float2 t;
            float4 o0, o1;
            t = *(float2*)&acc[j][0]; o0.x = t.x * s; o0.y = t.y * s;
            t = *(float2*)&acc[j][1]; o0.z = t.x * s; o0.w = t.y * s;
            t = *(float2*)&acc[j][2]; o1.x = t.x * s; o1.y = t.y * s;
            t = *(float2*)&acc[j][3]; o1.z = t.x * s; o1.w = t.y * s;
            float4* orow = (float4*)(out + (size_t)e * O_N);
            orow[tx]      = o0;
            orow[tx + 32] = o1;
        }
    }
}

// ---------------------------------------------------------------------------
extern "C" void kernel_launch(void* const* d_in, const int* in_sizes, int n_in,
                              void* d_out, int out_size) {
    const float* x  = (const float*)d_in[0];   // (E, I)  float32
    const float* cs = (const float*)d_in[1];   // (E, R)  float32
    const float* W  = (const float*)d_in[2];   // (R, I, O) float32
    // d_in[3] = edge_index: mathematically unused by the reference.
    float* out = (float*)d_out;                // (E, O) float32

    (void)in_sizes; (void)n_in; (void)out_size;

    const int smem_bytes = (R_N * O_N + TILE_E * R_N + TILE_E) * (int)sizeof(float);
    // >48KB dynamic smem requires opt-in; idempotent, capture-safe (non-stream API).
    cudaFuncSetAttribute(rgcn_kernel, cudaFuncAttributeMaxDynamicSharedMemorySize,
                         smem_bytes);

    wsum_kernel<<<R_N, 1024>>>(W);

    const int grid = (E_N + TILE_E - 1) / TILE_E;   // 1563
    rgcn_kernel<<<grid, 256, smem_bytes>>>(x, cs, out);
}